// round 6
// baseline (speedup 1.0000x reference)
#include <cuda_runtime.h>
#include <stdint.h>

// Fixed-shape problem constants
#define HH 352
#define WW 1216
#define PP 65536
#define CC 64
#define BB 2
#define HW (HH * WW)            // 428032 (divisible by 4)
#define NPIX (BB * HW)          // 856064
#define MAXC 8                  // per-pixel candidate capacity (= reference K)

// Scratch (__device__ globals: allocation-free)
__device__ int    d_count[NPIX];
__device__ uint2  d_cand[NPIX * MAXC];          // {pid, bitcast(weight)}
__device__ float  d_featsT[BB * PP * CC];       // src transposed to [B*P, C]

#define T_TILES (PP / 32 * (CC / 32) * BB)      // 8192 transpose tiles
#define Z_BLOCKS (NPIX / 4 / 256)               // 836 zero blocks (exact)

// ------------------------------------------------- transpose + zero counts (fused)
__global__ void __launch_bounds__(256)
prep_kernel(const float* __restrict__ src) {
    int bid = blockIdx.x;
    int tid = threadIdx.x;

    if (bid < T_TILES) {
        // src [B, C, P] -> d_featsT [B*P, C], 32x32 smem tile
        __shared__ float tile[32][33];
        int pb   = bid & (PP / 32 - 1);
        int rest = bid >> 11;
        int cb   = rest & 1;
        int b    = rest >> 1;
        int tx = tid & 31, ty = tid >> 5;
        int pbase = pb * 32, cbase = cb * 32;
        const float* sb = src + (size_t)b * CC * PP;
        #pragma unroll
        for (int j = 0; j < 4; j++) {
            int c = cbase + ty + j * 8;
            tile[ty + j * 8][tx] = sb[(size_t)c * PP + pbase + tx];
        }
        __syncthreads();
        float* ob = d_featsT + ((size_t)b * PP) * CC;
        #pragma unroll
        for (int j = 0; j < 4; j++) {
            int p = pbase + ty + j * 8;
            ob[(size_t)p * CC + cbase + tx] = tile[tx][ty + j * 8];
        }
    } else {
        int z = (bid - T_TILES) * 256 + tid;    // 0 .. NPIX/4-1
        ((int4*)d_count)[z] = make_int4(0, 0, 0, 0);
    }
}

// ------------------------------------------------- build candidate lists
// r = 3/1216 NDC. Row pitch 2/352 > 2r -> only row i0 qualifies.
// Col pitch 2/1216, 2r spans <=3 centers -> only j0-1..j0+1.
__global__ void __launch_bounds__(256)
build_kernel(const float* __restrict__ pts) {
    int t = blockIdx.x * blockDim.x + threadIdx.x;
    if (t >= BB * PP) return;
    int b = t >> 16;

    float x = pts[3 * t + 0];
    float y = pts[3 * t + 1];
    float z = pts[3 * t + 2];

    const float r2     = (3.0f / 1216.0f) * (3.0f / 1216.0f);
    const float inv_r2 = 1216.0f * 1216.0f / 9.0f;

    int i0 = (int)floorf((y + 1.0f) * 0.5f * (float)HH);
    int j0 = (int)floorf((x + 1.0f) * 0.5f * (float)WW);

    if (!(z > 0.0f) || i0 < 0 || i0 >= HH) return;

    float yc  = ((float)i0 + 0.5f) * (2.0f / (float)HH) - 1.0f;
    float fy2 = (y - yc) * (y - yc);

    #pragma unroll
    for (int dxi = -1; dxi <= 1; dxi++) {
        int jj = j0 + dxi;
        if (jj < 0 || jj >= WW) continue;
        float xc = ((float)jj + 0.5f) * (2.0f / (float)WW) - 1.0f;
        float fx = x - xc;
        float d2 = fx * fx + fy2;
        if (d2 < r2) {
            float alpha = 1.0f - sqrtf(fmaxf(d2 * inv_r2, 0.001f));
            int pix = (b * HH + i0) * WW + jj;
            int idx = atomicAdd(&d_count[pix], 1);
            if (idx < MAXC)
                d_cand[pix * MAXC + idx] = make_uint2((unsigned)t, __float_as_uint(alpha));
        }
    }
}

// ------------------------------------------------- gather
// Thread = 4 consecutive pixels x 4 channels. Accumulators are pixel-major
// float4s -> output is 4 direct STG.128 stores, no register shuffling.
__global__ void __launch_bounds__(256, 6)
gather_kernel(float* __restrict__ out) {
    int q = blockIdx.x * 256 + threadIdx.x;     // quad index 0..NPIX/4-1
    int g = blockIdx.y;                          // channel group 0..15 (4 ch each)
    int pix0 = q * 4;

    int4 cnt = ((const int4*)d_count)[q];

    // acc[c] = channel (g*4+c) values for pixels pix0..pix0+3
    float4 a0 = make_float4(0.f, 0.f, 0.f, 0.f);
    float4 a1 = a0, a2 = a0, a3 = a0;

    int ns[4] = { cnt.x, cnt.y, cnt.z, cnt.w };

    #pragma unroll
    for (int pl = 0; pl < 4; pl++) {
        int n = ns[pl] < MAXC ? ns[pl] : MAXC;
        const uint2* cb = d_cand + (size_t)(pix0 + pl) * MAXC;
        for (int i = 0; i < n; i++) {
            uint2 e = __ldg(&cb[i]);
            float w = __uint_as_float(e.y);
            float4 f = __ldg((const float4*)(d_featsT + (size_t)e.x * CC + g * 4));
            if (pl == 0) { a0.x += w * f.x; a1.x += w * f.y; a2.x += w * f.z; a3.x += w * f.w; }
            if (pl == 1) { a0.y += w * f.x; a1.y += w * f.y; a2.y += w * f.z; a3.y += w * f.w; }
            if (pl == 2) { a0.z += w * f.x; a1.z += w * f.y; a2.z += w * f.z; a3.z += w * f.w; }
            if (pl == 3) { a0.w += w * f.x; a1.w += w * f.y; a2.w += w * f.z; a3.w += w * f.w; }
        }
    }

    int b   = pix0 / HW;
    int loc = pix0 - b * HW;
    float* base = out + (size_t)b * CC * HW + (size_t)(g * 4) * HW + loc;

    __stcs((float4*)(base + 0 * (size_t)HW), a0);
    __stcs((float4*)(base + 1 * (size_t)HW), a1);
    __stcs((float4*)(base + 2 * (size_t)HW), a2);
    __stcs((float4*)(base + 3 * (size_t)HW), a3);
}

extern "C" void kernel_launch(void* const* d_in, const int* in_sizes, int n_in,
                              void* d_out, int out_size) {
    const float* pts = (const float*)d_in[0];   // [B, P, 3]
    const float* src = (const float*)d_in[1];   // [B, C, P]
    float* out = (float*)d_out;                 // [B, C, H, W]

    prep_kernel<<<T_TILES + Z_BLOCKS, 256>>>(src);
    build_kernel<<<(BB * PP) / 256, 256>>>(pts);

    dim3 ggrid(NPIX / 4 / 256, CC / 4);         // (836, 16)
    gather_kernel<<<ggrid, 256>>>(out);
}

// round 7
// speedup vs baseline: 1.3822x; 1.3822x over previous
#include <cuda_runtime.h>
#include <stdint.h>

// Fixed-shape problem constants
#define HH 352
#define WW 1216
#define PP 65536
#define CC 64
#define BB 2
#define HW (HH * WW)            // 428032
#define NPIX (BB * HW)          // 856064
#define MAXC 8                  // per-pixel candidate capacity (= reference K)

// Scratch (__device__ globals: allocation-free)
__device__ int    d_count[NPIX];
__device__ uint2  d_cand[NPIX * MAXC];          // {pid, bitcast(weight)}
__device__ float  d_featsT[BB * PP * CC];       // src transposed to [B*P, C]

#define T_TILES (PP / 32 * (CC / 32) * BB)      // 8192 transpose tiles
#define Z_BLOCKS (NPIX / 4 / 256)               // 836 zero blocks (exact)

// ------------------------------------------------- transpose + zero counts (fused)
__global__ void __launch_bounds__(256)
prep_kernel(const float* __restrict__ src) {
    int bid = blockIdx.x;
    int tid = threadIdx.x;

    if (bid < T_TILES) {
        // src [B, C, P] -> d_featsT [B*P, C], 32x32 smem tile
        __shared__ float tile[32][33];
        int pb   = bid & (PP / 32 - 1);
        int rest = bid >> 11;
        int cb   = rest & 1;
        int b    = rest >> 1;
        int tx = tid & 31, ty = tid >> 5;
        int pbase = pb * 32, cbase = cb * 32;
        const float* sb = src + (size_t)b * CC * PP;
        #pragma unroll
        for (int j = 0; j < 4; j++) {
            int c = cbase + ty + j * 8;
            tile[ty + j * 8][tx] = sb[(size_t)c * PP + pbase + tx];
        }
        __syncthreads();
        float* ob = d_featsT + ((size_t)b * PP) * CC;
        #pragma unroll
        for (int j = 0; j < 4; j++) {
            int p = pbase + ty + j * 8;
            ob[(size_t)p * CC + cbase + tx] = tile[tx][ty + j * 8];
        }
    } else {
        int z = (bid - T_TILES) * 256 + tid;    // 0 .. NPIX/4-1
        ((int4*)d_count)[z] = make_int4(0, 0, 0, 0);
    }
}

// ------------------------------------------------- build candidate lists
// r = 3/1216 NDC. Row pitch 2/352 > 2r -> only row i0 qualifies.
// Col pitch 2/1216, 2r spans <=3 centers -> only j0-1..j0+1.
__global__ void __launch_bounds__(256)
build_kernel(const float* __restrict__ pts) {
    int t = blockIdx.x * blockDim.x + threadIdx.x;
    if (t >= BB * PP) return;
    int b = t >> 16;

    float x = pts[3 * t + 0];
    float y = pts[3 * t + 1];
    float z = pts[3 * t + 2];

    const float r2     = (3.0f / 1216.0f) * (3.0f / 1216.0f);
    const float inv_r2 = 1216.0f * 1216.0f / 9.0f;

    int i0 = (int)floorf((y + 1.0f) * 0.5f * (float)HH);
    int j0 = (int)floorf((x + 1.0f) * 0.5f * (float)WW);

    if (!(z > 0.0f) || i0 < 0 || i0 >= HH) return;

    float yc  = ((float)i0 + 0.5f) * (2.0f / (float)HH) - 1.0f;
    float fy2 = (y - yc) * (y - yc);

    #pragma unroll
    for (int dxi = -1; dxi <= 1; dxi++) {
        int jj = j0 + dxi;
        if (jj < 0 || jj >= WW) continue;
        float xc = ((float)jj + 0.5f) * (2.0f / (float)WW) - 1.0f;
        float fx = x - xc;
        float d2 = fx * fx + fy2;
        if (d2 < r2) {
            float alpha = 1.0f - sqrtf(fmaxf(d2 * inv_r2, 0.001f));
            int pix = (b * HH + i0) * WW + jj;
            int idx = atomicAdd(&d_count[pix], 1);
            if (idx < MAXC)
                d_cand[pix * MAXC + idx] = make_uint2((unsigned)t, __float_as_uint(alpha));
        }
    }
}

// ------------------------------------------------- gather
// Thread = one pixel x 8 channels (proven R5 form).
// Changes: unrolled guarded candidate loop (independent slot chains),
// streaming output stores (__stcs) to keep cand/feat L2-resident.
__global__ void __launch_bounds__(256, 8)
gather_kernel(float* __restrict__ out) {
    int pix = blockIdx.x * 256 + threadIdx.x;
    int g   = blockIdx.y;

    int n = d_count[pix];
    n = n < MAXC ? n : MAXC;

    float4 accA = make_float4(0.f, 0.f, 0.f, 0.f);
    float4 accB = make_float4(0.f, 0.f, 0.f, 0.f);
    const uint2* cb = d_cand + (size_t)pix * MAXC;

    #pragma unroll
    for (int i = 0; i < MAXC; i++) {
        if (i < n) {
            uint2 e = __ldg(&cb[i]);
            float w = __uint_as_float(e.y);
            const float4* fp = (const float4*)(d_featsT + (size_t)e.x * CC + g * 8);
            float4 a = __ldg(fp);
            float4 c = __ldg(fp + 1);
            accA.x += w * a.x; accA.y += w * a.y; accA.z += w * a.z; accA.w += w * a.w;
            accB.x += w * c.x; accB.y += w * c.y; accB.z += w * c.z; accB.w += w * c.w;
        }
    }

    int b   = pix / HW;
    int loc = pix - b * HW;
    float* ob = out + (size_t)b * CC * HW + (size_t)(g * 8) * HW + loc;
    __stcs(ob + 0 * (size_t)HW, accA.x);
    __stcs(ob + 1 * (size_t)HW, accA.y);
    __stcs(ob + 2 * (size_t)HW, accA.z);
    __stcs(ob + 3 * (size_t)HW, accA.w);
    __stcs(ob + 4 * (size_t)HW, accB.x);
    __stcs(ob + 5 * (size_t)HW, accB.y);
    __stcs(ob + 6 * (size_t)HW, accB.z);
    __stcs(ob + 7 * (size_t)HW, accB.w);
}

extern "C" void kernel_launch(void* const* d_in, const int* in_sizes, int n_in,
                              void* d_out, int out_size) {
    const float* pts = (const float*)d_in[0];   // [B, P, 3]
    const float* src = (const float*)d_in[1];   // [B, C, P]
    float* out = (float*)d_out;                 // [B, C, H, W]

    prep_kernel<<<T_TILES + Z_BLOCKS, 256>>>(src);
    build_kernel<<<(BB * PP) / 256, 256>>>(pts);

    dim3 ggrid(NPIX / 256, 8);                  // (3344, 8)
    gather_kernel<<<ggrid, 256>>>(out);
}

// round 8
// speedup vs baseline: 1.4565x; 1.0538x over previous
#include <cuda_runtime.h>
#include <stdint.h>

// Fixed-shape problem constants
#define HH 352
#define WW 1216
#define PP 65536
#define CC 64
#define BB 2
#define HW (HH * WW)            // 428032
#define NPIX (BB * HW)          // 856064
#define MAXC 8                  // per-pixel candidate capacity (= reference K)

// Scratch (__device__ globals: allocation-free)
__device__ int    d_count[NPIX];
__device__ uint2  d_cand[NPIX * MAXC];          // {pid, bitcast(weight)}
__device__ float  d_featsT[BB * PP * CC];       // src transposed to [B*P, C]

#define T_TILES (PP / 32 * (CC / 32) * BB)      // 8192 transpose tiles
#define Z_BLOCKS (NPIX / 4 / 256)               // 836 zero blocks (exact)

// ------------------------------------------------- transpose + zero counts (fused)
__global__ void __launch_bounds__(256)
prep_kernel(const float* __restrict__ src) {
    int bid = blockIdx.x;
    int tid = threadIdx.x;

    if (bid < T_TILES) {
        // src [B, C, P] -> d_featsT [B*P, C], 32x32 smem tile
        __shared__ float tile[32][33];
        int pb   = bid & (PP / 32 - 1);
        int rest = bid >> 11;
        int cb   = rest & 1;
        int b    = rest >> 1;
        int tx = tid & 31, ty = tid >> 5;
        int pbase = pb * 32, cbase = cb * 32;
        const float* sb = src + (size_t)b * CC * PP;
        #pragma unroll
        for (int j = 0; j < 4; j++) {
            int c = cbase + ty + j * 8;
            tile[ty + j * 8][tx] = sb[(size_t)c * PP + pbase + tx];
        }
        __syncthreads();
        float* ob = d_featsT + ((size_t)b * PP) * CC;
        #pragma unroll
        for (int j = 0; j < 4; j++) {
            int p = pbase + ty + j * 8;
            ob[(size_t)p * CC + cbase + tx] = tile[tx][ty + j * 8];
        }
    } else {
        int z = (bid - T_TILES) * 256 + tid;    // 0 .. NPIX/4-1
        ((int4*)d_count)[z] = make_int4(0, 0, 0, 0);
    }
}

// ------------------------------------------------- build candidate lists
// r = 3/1216 NDC. Row pitch 2/352 > 2r -> only row i0 qualifies.
// Col pitch 2/1216, 2r spans <=3 centers -> only j0-1..j0+1.
__global__ void __launch_bounds__(256)
build_kernel(const float* __restrict__ pts) {
    int t = blockIdx.x * blockDim.x + threadIdx.x;
    if (t >= BB * PP) return;
    int b = t >> 16;

    float x = pts[3 * t + 0];
    float y = pts[3 * t + 1];
    float z = pts[3 * t + 2];

    const float r2     = (3.0f / 1216.0f) * (3.0f / 1216.0f);
    const float inv_r2 = 1216.0f * 1216.0f / 9.0f;

    int i0 = (int)floorf((y + 1.0f) * 0.5f * (float)HH);
    int j0 = (int)floorf((x + 1.0f) * 0.5f * (float)WW);

    if (!(z > 0.0f) || i0 < 0 || i0 >= HH) return;

    float yc  = ((float)i0 + 0.5f) * (2.0f / (float)HH) - 1.0f;
    float fy2 = (y - yc) * (y - yc);

    #pragma unroll
    for (int dxi = -1; dxi <= 1; dxi++) {
        int jj = j0 + dxi;
        if (jj < 0 || jj >= WW) continue;
        float xc = ((float)jj + 0.5f) * (2.0f / (float)WW) - 1.0f;
        float fx = x - xc;
        float d2 = fx * fx + fy2;
        if (d2 < r2) {
            float alpha = 1.0f - sqrtf(fmaxf(d2 * inv_r2, 0.001f));
            int pix = (b * HH + i0) * WW + jj;
            int idx = atomicAdd(&d_count[pix], 1);
            if (idx < MAXC)
                d_cand[pix * MAXC + idx] = make_uint2((unsigned)t, __float_as_uint(alpha));
        }
    }
}

// ------------------------------------------------- gather
// Thread = one pixel, ALL 64 channels. Candidate list read ONCE into
// registers (4 guarded uint4 loads), then 8 channel-group passes of
// accumulate + streaming stores. Counts/cand traffic cut 8x vs R7.
__global__ void __launch_bounds__(256, 4)
gather_kernel(float* __restrict__ out) {
    int pix = blockIdx.x * 256 + threadIdx.x;

    int n = d_count[pix];
    n = n < MAXC ? n : MAXC;

    // Hoist candidate entries into registers.
    const uint4* cb4 = (const uint4*)(d_cand + (size_t)pix * MAXC);
    uint4 e01 = make_uint4(0,0,0,0), e23 = e01, e45 = e01, e67 = e01;
    if (n > 0) e01 = __ldg(&cb4[0]);
    if (n > 2) e23 = __ldg(&cb4[1]);
    if (n > 4) e45 = __ldg(&cb4[2]);
    if (n > 6) e67 = __ldg(&cb4[3]);

    unsigned pid[MAXC];
    float    wgt[MAXC];
    pid[0] = e01.x; wgt[0] = __uint_as_float(e01.y);
    pid[1] = e01.z; wgt[1] = __uint_as_float(e01.w);
    pid[2] = e23.x; wgt[2] = __uint_as_float(e23.y);
    pid[3] = e23.z; wgt[3] = __uint_as_float(e23.w);
    pid[4] = e45.x; wgt[4] = __uint_as_float(e45.y);
    pid[5] = e45.z; wgt[5] = __uint_as_float(e45.w);
    pid[6] = e67.x; wgt[6] = __uint_as_float(e67.y);
    pid[7] = e67.z; wgt[7] = __uint_as_float(e67.w);

    int b   = pix / HW;
    int loc = pix - b * HW;
    float* ob = out + (size_t)b * CC * HW + loc;

    #pragma unroll
    for (int g = 0; g < 8; g++) {
        float4 accA = make_float4(0.f, 0.f, 0.f, 0.f);
        float4 accB = make_float4(0.f, 0.f, 0.f, 0.f);
        #pragma unroll
        for (int i = 0; i < MAXC; i++) {
            if (i < n) {
                const float4* fp = (const float4*)(d_featsT + (size_t)pid[i] * CC + g * 8);
                float4 a = __ldg(fp);
                float4 c = __ldg(fp + 1);
                float w = wgt[i];
                accA.x += w * a.x; accA.y += w * a.y; accA.z += w * a.z; accA.w += w * a.w;
                accB.x += w * c.x; accB.y += w * c.y; accB.z += w * c.z; accB.w += w * c.w;
            }
        }
        float* oc = ob + (size_t)(g * 8) * HW;
        __stcs(oc + 0 * (size_t)HW, accA.x);
        __stcs(oc + 1 * (size_t)HW, accA.y);
        __stcs(oc + 2 * (size_t)HW, accA.z);
        __stcs(oc + 3 * (size_t)HW, accA.w);
        __stcs(oc + 4 * (size_t)HW, accB.x);
        __stcs(oc + 5 * (size_t)HW, accB.y);
        __stcs(oc + 6 * (size_t)HW, accB.z);
        __stcs(oc + 7 * (size_t)HW, accB.w);
    }
}

extern "C" void kernel_launch(void* const* d_in, const int* in_sizes, int n_in,
                              void* d_out, int out_size) {
    const float* pts = (const float*)d_in[0];   // [B, P, 3]
    const float* src = (const float*)d_in[1];   // [B, C, P]
    float* out = (float*)d_out;                 // [B, C, H, W]

    prep_kernel<<<T_TILES + Z_BLOCKS, 256>>>(src);
    build_kernel<<<(BB * PP) / 256, 256>>>(pts);

    gather_kernel<<<NPIX / 256, 256>>>(out);    // 3344 blocks
}